// round 16
// baseline (speedup 1.0000x reference)
#include <cuda_runtime.h>
#include <math.h>

#define BB    4
#define SSEQ  4096
#define IND   1024
#define OUTD  1024
#define EE    8
#define LSCALE 512.0f
#define GRID  512
#define CPB   128            // CTAs per batch

// ---- scratch (device globals; allocation is forbidden) ----
__device__ float    g_seg[BB * IND];   // 16 KB : per-batch column sums (zeroed by gater)
__device__ float    g_coef[BB * 2];
__device__ int      g_idx[BB * 2];
__device__ unsigned g_arrive[BB];      // per-batch stage-1 arrivals (reset by gater)
__device__ unsigned g_flag[BB];        // per-batch gating-done flags (reset by last finisher)
__device__ unsigned g_done[BB];        // per-batch stage-2 completion counters

typedef unsigned long long u64;

__device__ __forceinline__ void fma2(u64& d, u64 a, u64 b) {
    asm("fma.rn.f32x2 %0, %1, %2, %0;" : "+l"(d) : "l"(a), "l"(b));
}
__device__ __forceinline__ float lo2(u64 v) { return __uint_as_float((unsigned)(v & 0xffffffffull)); }
__device__ __forceinline__ float hi2(u64 v) { return __uint_as_float((unsigned)(v >> 32)); }

__device__ __forceinline__ void stcs4(float* p, float4 v) {
    asm volatile("st.global.cs.v4.f32 [%0], {%1, %2, %3, %4};"
                 :: "l"(p), "f"(v.x), "f"(v.y), "f"(v.z), "f"(v.w));
}

// ------------------------------------------------------------------
// Fused persistent kernel, per-batch barriers, DOTS BEFORE BARRIER.
// 512 CTAs, 256 thr, hard 64-reg cap: 4 CTA/SM x 148 = 592 >= 512 ->
// all CTAs wave-1 resident, spins deadlock-free.
//   1. stage lora_A (all 8 experts) into shared [e][k]
//   2. column sums of this CTA's 32 rows (DRAM read) + REDG + arrive
//   3. gater CTA (128th arriver of batch b): gating, release flag[b]
//      EVERYONE (incl. gater afterwards): all-8 expert dots -> h in
//      shared. Gating overlaps dots -> spin ~= 0.
//   4. select (e0,e1), scale, store phase (proven).
// Dots: 2 token-halves x 2 expert-halves; acc = 16 u64 per subpass.
// ------------------------------------------------------------------
#define TOKB 32

__global__ void __launch_bounds__(256, 4) fused_moe(const float* __restrict__ x,
                                                    const float* __restrict__ lora_A,
                                                    const float* __restrict__ lora_B,
                                                    const float* __restrict__ gate_w,
                                                    const float* __restrict__ gate_b,
                                                    float* __restrict__ out) {
    __shared__ float    A_s[EE * IND];  // 32 KB : all experts' A rows [e][k]
    __shared__ float    h_s[TOKB * EE]; //  1 KB : all-expert dots for this tile
    __shared__ float2   cs[TOKB];
    __shared__ float    dots[EE];
    __shared__ unsigned s_last;
    __shared__ int2     s_ix;
    __shared__ float2   s_cf;

    const int tid  = threadIdx.x;
    const int w    = tid >> 5;
    const int lane = tid & 31;
    const int b       = blockIdx.x >> 7;            // 128 CTAs per batch
    const int tokbase = (blockIdx.x & 127) * TOKB;

    // ---- 1. stage all of lora_A (coalesced float4 copy) ----
    #pragma unroll
    for (int j = 0; j < 8; ++j)
        ((float4*)A_s)[tid + j * 256] = ((const float4*)lora_A)[tid + j * 256];

    // ---- 2. column sums (proven loop) + REDG ----
    {
        const float* xp = x + ((size_t)b * SSEQ + tokbase) * IND + tid * 4;
        float4 a4 = make_float4(0.f, 0.f, 0.f, 0.f);
        #pragma unroll 8
        for (int r = 0; r < TOKB; ++r) {
            float4 v = *(const float4*)(xp + (size_t)r * IND);
            a4.x += v.x; a4.y += v.y; a4.z += v.z; a4.w += v.w;
        }
        float* dst = &g_seg[b * IND + tid * 4];
        atomicAdd(dst + 0, a4.x);
        atomicAdd(dst + 1, a4.y);
        atomicAdd(dst + 2, a4.z);
        atomicAdd(dst + 3, a4.w);
    }

    // ---- per-batch arrive (also orders A_s before dots) ----
    __syncthreads();
    if (tid == 0) {
        unsigned old;
        asm volatile("atom.acq_rel.gpu.global.add.u32 %0, [%1], 1;"
                     : "=r"(old) : "l"(&g_arrive[b]) : "memory");
        s_last = (old == (unsigned)(CPB - 1)) ? 1u : 0u;
    }
    __syncthreads();

    // ---- 3a. gater CTA: gating for batch b, release flag ----
    if (s_last) {
        {
            float s = 0.f;
            #pragma unroll
            for (int i = 0; i < 8; ++i) {
                int k = lane * 4 + i * 128;
                float4 a = *(const float4*)&g_seg[b * IND + k];
                float4 g = *(const float4*)&gate_w[w * IND + k];
                s += a.x * g.x + a.y * g.y + a.z * g.z + a.w * g.w;
            }
            #pragma unroll
            for (int o = 16; o; o >>= 1) s += __shfl_xor_sync(0xffffffffu, s, o);
            if (lane == 0) dots[w] = s * (1.0f / (float)SSEQ) + gate_b[w];
        }
        __syncthreads();

        // zero this batch's g_seg slice for the next replay (256 float4)
        ((float4*)&g_seg[b * IND])[tid] = make_float4(0.f, 0.f, 0.f, 0.f);

        if (tid == 0) {
            float l[EE]; float mx = -1e30f;
            #pragma unroll
            for (int i = 0; i < EE; ++i) { l[i] = dots[i]; mx = fmaxf(mx, l[i]); }
            float sum = 0.f;
            #pragma unroll
            for (int i = 0; i < EE; ++i) { l[i] = expf(l[i] - mx); sum += l[i]; }
            int i0 = 0;
            #pragma unroll
            for (int i = 1; i < EE; ++i) if (l[i] > l[i0]) i0 = i;   // ties -> lowest idx
            int i1 = (i0 == 0) ? 1 : 0;
            #pragma unroll
            for (int i = 0; i < EE; ++i) if (i != i0 && l[i] > l[i1]) i1 = i;
            g_idx[b * 2] = i0;  g_idx[b * 2 + 1] = i1;
            float f = LSCALE / sum;
            g_coef[b * 2]     = l[i0] * f;
            g_coef[b * 2 + 1] = l[i1] * f;
            g_arrive[b] = 0;                        // safe: all 128 arrived
        }
        __syncthreads();                            // coef/idx + zeroing done
        if (tid == 0)
            asm volatile("st.release.gpu.global.u32 [%0], %1;"
                         :: "l"(&g_flag[b]), "r"(1u) : "memory");
        __syncthreads();
    }

    // ---- 3b. ALL CTAs: all-8 expert dots -> h_s (overlaps gating) ----
    #pragma unroll 1
    for (int th = 0; th < 2; ++th) {                // token halves (16 each)
        const int trow = th * 16 + w * 2;           // this warp's 2 tokens
        const float* xw = x + ((size_t)(b * SSEQ + tokbase + trow)) * IND;
        #pragma unroll 1
        for (int eh = 0; eh < 2; ++eh) {            // expert halves (4 each)
            u64 acc[2][4];
            #pragma unroll
            for (int t = 0; t < 2; ++t)
                #pragma unroll
                for (int ee = 0; ee < 4; ++ee) acc[t][ee] = 0ull;

            const float* Ah = A_s + (eh * 4) * IND;

            #pragma unroll 4
            for (int c = 0; c < 8; ++c) {
                const int koff = c * 128 + lane * 4;
                double2 xv0 = *(const double2*)(xw + koff);
                double2 xv1 = *(const double2*)(xw + IND + koff);
                u64 x0lo = __double_as_longlong(xv0.x), x0hi = __double_as_longlong(xv0.y);
                u64 x1lo = __double_as_longlong(xv1.x), x1hi = __double_as_longlong(xv1.y);
                #pragma unroll
                for (int ee = 0; ee < 4; ++ee) {
                    double2 av = *(const double2*)&Ah[ee * IND + koff];
                    u64 alo = __double_as_longlong(av.x);
                    u64 ahi = __double_as_longlong(av.y);
                    fma2(acc[0][ee], x0lo, alo);
                    fma2(acc[0][ee], x0hi, ahi);
                    fma2(acc[1][ee], x1lo, alo);
                    fma2(acc[1][ee], x1hi, ahi);
                }
            }

            #pragma unroll
            for (int t = 0; t < 2; ++t) {
                float v[4];
                #pragma unroll
                for (int ee = 0; ee < 4; ++ee) v[ee] = lo2(acc[t][ee]) + hi2(acc[t][ee]);
                #pragma unroll
                for (int off = 16; off; off >>= 1)
                    #pragma unroll
                    for (int ee = 0; ee < 4; ++ee)
                        v[ee] += __shfl_xor_sync(0xffffffffu, v[ee], off);
                if (lane == 0)
                    *(float4*)&h_s[(trow + t) * EE + eh * 4] =
                        make_float4(v[0], v[1], v[2], v[3]);
            }
        }
    }
    __syncthreads();                                // h_s complete

    // ---- 4. spin (usually already released), select, store ----
    if (tid == 0) {
        unsigned f = 0;
        do {
            asm volatile("ld.acquire.gpu.global.u32 %0, [%1];"
                         : "=r"(f) : "l"(&g_flag[b]) : "memory");
            if (f) break;
            __nanosleep(64);
        } while (1);
        s_ix = *(const int2*)&g_idx[b * 2];
        s_cf = *(const float2*)&g_coef[b * 2];
    }
    __syncthreads();
    const int   e0 = s_ix.x, e1 = s_ix.y;
    const float w0 = s_cf.x, w1 = s_cf.y;

    if (tid < TOKB)
        cs[tid] = make_float2(w0 * h_s[tid * EE + e0], w1 * h_s[tid * EE + e1]);

    float4 B0 = *(const float4*)&lora_B[e0 * OUTD + tid * 4];
    float4 B1 = *(const float4*)&lora_B[e1 * OUTD + tid * 4];
    __syncthreads();

    float* ob = out + ((size_t)b * SSEQ + tokbase) * OUTD + tid * 4;
    #pragma unroll 4
    for (int i = 0; i < TOKB; ++i) {
        float2 cc = cs[i];
        float4 v;
        v.x = cc.x * B0.x + cc.y * B1.x;
        v.y = cc.x * B0.y + cc.y * B1.y;
        v.z = cc.x * B0.z + cc.y * B1.z;
        v.w = cc.x * B0.w + cc.y * B1.w;
        stcs4(ob + (size_t)i * OUTD, v);
    }

    // ---- per-batch flag reset for the next graph replay ----
    __syncthreads();
    if (tid == 0) {
        unsigned old;
        asm volatile("atom.acq_rel.gpu.global.add.u32 %0, [%1], 1;"
                     : "=r"(old) : "l"(&g_done[b]) : "memory");
        if (old == (unsigned)(CPB - 1)) {
            g_flag[b] = 0;
            g_done[b] = 0;
        }
    }
}

// ------------------------------------------------------------------
extern "C" void kernel_launch(void* const* d_in, const int* in_sizes, int n_in,
                              void* d_out, int out_size) {
    const float* x      = (const float*)d_in[0];
    const float* lora_A = (const float*)d_in[1];
    const float* lora_B = (const float*)d_in[2];
    const float* gate_w = (const float*)d_in[3];
    const float* gate_b = (const float*)d_in[4];
    float* out = (float*)d_out;

    fused_moe<<<GRID, 256>>>(x, lora_A, lora_B, gate_w, gate_b, out);
}